// round 1
// baseline (speedup 1.0000x reference)
#include <cuda_runtime.h>
#include <cstdint>
#include <cstddef>

// ---------------- problem constants ----------------
#define T_STEPS 512
#define BB      64
#define EE      512
#define HH      1024
#define DD      1536
#define NG      4096      // 4*H gate columns (order: f, i, c, o)
#define NCLS    10

// ---------------- recurrent kernel config ----------------
#define GBLK 64           // persistent grid size (<= #SMs, co-resident)
#define JPB  16           // j (hidden units) per block
#define NPB  64           // gate-columns per block = 4 * JPB
#define KC   32           // K chunk
#define NCHUNK (HH / KC)  // 32

// ---------------- x-GEMM config ----------------
#define XBM 128
#define XBN 128
#define XBK 16
#define XKCH (EE / XBK)   // 32

// ---------------- device scratch (allocation-free) ----------------
__device__ float d_Gx[(size_t)T_STEPS * BB * NG];   // 512 MB: x-side gate preacts [t][b][n]
__device__ float d_Xr[(size_t)BB * T_STEPS * EE];   // tf32-rounded input
__device__ float d_Whr[(size_t)NG * HH];            // tf32-rounded recurrent weights [n][k]
__device__ float d_Wxr[(size_t)NG * EE];            // tf32-rounded input weights   [n][e]
__device__ float d_h[2][BB * HH];                   // double-buffered hidden state (tf32-rounded)
__device__ float d_hfin[BB * HH];                   // exact fp32 final h
__device__ int   d_bar[T_STEPS];                    // per-step grid barrier counters

// ---------------- helpers ----------------
__device__ __forceinline__ unsigned f2tf32(float x) {
    unsigned r;
    asm("cvt.rna.tf32.f32 %0, %1;" : "=r"(r) : "f"(x));
    return r;
}

__device__ __forceinline__ void mma_tf32(float& c0, float& c1, float& c2, float& c3,
                                         unsigned a0, unsigned a1, unsigned a2, unsigned a3,
                                         unsigned b0, unsigned b1) {
    asm volatile(
        "mma.sync.aligned.m16n8k8.row.col.f32.tf32.tf32.f32 "
        "{%0,%1,%2,%3},{%4,%5,%6,%7},{%8,%9},{%0,%1,%2,%3};"
        : "+f"(c0), "+f"(c1), "+f"(c2), "+f"(c3)
        : "r"(a0), "r"(a1), "r"(a2), "r"(a3), "r"(b0), "r"(b1));
}

__device__ __forceinline__ uint32_t saddr(const void* p) {
    return (uint32_t)__cvta_generic_to_shared(p);
}
__device__ __forceinline__ void cpasync16(uint32_t dst, const void* src) {
    asm volatile("cp.async.cg.shared.global [%0], [%1], 16;" :: "r"(dst), "l"(src));
}
#define CP_COMMIT() asm volatile("cp.async.commit_group;")
#define CP_WAIT(N)  asm volatile("cp.async.wait_group %0;" :: "n"(N))

// ---------------- init: zero barrier counters + h buffers ----------------
__global__ void k_init() {
    int i = blockIdx.x * blockDim.x + threadIdx.x;
    if (i < T_STEPS) d_bar[i] = 0;
    for (int j = i; j < BB * HH; j += gridDim.x * blockDim.x) {
        d_h[0][j] = 0.f;
        d_h[1][j] = 0.f;
    }
}

// ---------------- prep: split + tf32-round weights ----------------
__global__ void k_prep_w(const float* __restrict__ Wf, const float* __restrict__ Wi,
                         const float* __restrict__ Wc, const float* __restrict__ Wo) {
    size_t idx = (size_t)blockIdx.x * blockDim.x + threadIdx.x;
    if (idx >= (size_t)4 * HH * DD) return;
    int d   = (int)(idx % DD);
    int rem = (int)(idx / DD);
    int j   = rem % HH;
    int g   = rem / HH;
    const float* W = (g == 0) ? Wf : (g == 1) ? Wi : (g == 2) ? Wc : Wo;
    float vr = __uint_as_float(f2tf32(W[(size_t)j * DD + d]));
    int n = g * HH + j;
    if (d < EE) d_Wxr[(size_t)n * EE + d]        = vr;
    else        d_Whr[(size_t)n * HH + (d - EE)] = vr;
}

__global__ void k_prep_x(const float* __restrict__ X) {
    size_t idx = (size_t)blockIdx.x * blockDim.x + threadIdx.x;
    if (idx < (size_t)BB * T_STEPS * EE)
        d_Xr[idx] = __uint_as_float(f2tf32(X[idx]));
}

// ---------------- x-side GEMM: Gx[t][b][n] = X @ Wx^T + bias ----------------
// C[r, n], r = b*T + t (natural X row order), written to Gx row (t*64 + b).
__global__ void __launch_bounds__(256) k_gx_gemm(const float* __restrict__ bf, const float* __restrict__ bi,
                                                 const float* __restrict__ bc, const float* __restrict__ bo) {
    __shared__ float As[2][XBM][XBK + 4];
    __shared__ float Bs[2][XBN][XBK + 4];

    const int tid = threadIdx.x;
    const int warp = tid >> 5, lane = tid & 31;
    const int g8 = lane >> 2, tg = lane & 3;
    const int m0 = blockIdx.y * XBM;
    const int n0 = blockIdx.x * XBN;
    const int wm = (warp & 3) * 32;
    const int wn = (warp >> 2) * 64;

    float acc[2][8][4];
#pragma unroll
    for (int a = 0; a < 2; a++)
#pragma unroll
        for (int b = 0; b < 8; b++)
#pragma unroll
            for (int c = 0; c < 4; c++) acc[a][b][c] = 0.f;

    auto load_chunk = [&](int c, int buf) {
        int k0 = c * XBK;
#pragma unroll
        for (int i = 0; i < 2; i++) {
            int q = tid + i * 256;
            int row = q >> 2, kq = q & 3;
            cpasync16(saddr(&As[buf][row][kq * 4]),
                      d_Xr + (size_t)(m0 + row) * EE + k0 + kq * 4);
            cpasync16(saddr(&Bs[buf][row][kq * 4]),
                      d_Wxr + (size_t)(n0 + row) * EE + k0 + kq * 4);
        }
    };

    load_chunk(0, 0);
    CP_COMMIT();

    for (int c = 0; c < XKCH; c++) {
        if (c + 1 < XKCH) {
            load_chunk(c + 1, (c + 1) & 1);
            CP_COMMIT();
            CP_WAIT(1);
        } else {
            CP_WAIT(0);
        }
        __syncthreads();
        const int buf = c & 1;
#pragma unroll
        for (int kk = 0; kk < XBK; kk += 8) {
            unsigned a[2][4];
#pragma unroll
            for (int mi = 0; mi < 2; mi++) {
                a[mi][0] = __float_as_uint(As[buf][wm + mi * 16 + g8][kk + tg]);
                a[mi][1] = __float_as_uint(As[buf][wm + mi * 16 + 8 + g8][kk + tg]);
                a[mi][2] = __float_as_uint(As[buf][wm + mi * 16 + g8][kk + tg + 4]);
                a[mi][3] = __float_as_uint(As[buf][wm + mi * 16 + 8 + g8][kk + tg + 4]);
            }
#pragma unroll
            for (int ni = 0; ni < 8; ni++) {
                unsigned b0 = __float_as_uint(Bs[buf][wn + ni * 8 + g8][kk + tg]);
                unsigned b1 = __float_as_uint(Bs[buf][wn + ni * 8 + g8][kk + tg + 4]);
                mma_tf32(acc[0][ni][0], acc[0][ni][1], acc[0][ni][2], acc[0][ni][3],
                         a[0][0], a[0][1], a[0][2], a[0][3], b0, b1);
                mma_tf32(acc[1][ni][0], acc[1][ni][1], acc[1][ni][2], acc[1][ni][3],
                         a[1][0], a[1][1], a[1][2], a[1][3], b0, b1);
            }
        }
        __syncthreads();
    }

    // epilogue: add bias, scatter rows r=(b,t) -> Gx row (t*64+b), contiguous in n
#pragma unroll
    for (int mi = 0; mi < 2; mi++) {
        int r0 = m0 + wm + mi * 16 + g8;
        int r1 = r0 + 8;
        size_t o0 = ((size_t)(r0 & (T_STEPS - 1)) * BB + (r0 >> 9)) * NG;
        size_t o1 = ((size_t)(r1 & (T_STEPS - 1)) * BB + (r1 >> 9)) * NG;
#pragma unroll
        for (int ni = 0; ni < 8; ni++) {
            int col = n0 + wn + ni * 8 + 2 * tg;
            int g = col >> 10;
            int jj = col & (HH - 1);
            const float* bp = (g == 0) ? bf : (g == 1) ? bi : (g == 2) ? bc : bo;
            float bv0 = bp[jj], bv1 = bp[jj + 1];
            float2 v0 = make_float2(acc[mi][ni][0] + bv0, acc[mi][ni][1] + bv1);
            float2 v1 = make_float2(acc[mi][ni][2] + bv0, acc[mi][ni][3] + bv1);
            *(float2*)(d_Gx + o0 + col) = v0;
            *(float2*)(d_Gx + o1 + col) = v1;
        }
    }
}

// ---------------- persistent recurrent kernel ----------------
// 64 blocks, each owns JPB=16 hidden units j (all 4 gates -> NPB=64 gate-cols).
// Per step: A[64,64] = h(t-1)[64,1024] @ Whr_slice^T, then gate math + c/h update.
__global__ void __launch_bounds__(256) k_lstm_rec() {
    __shared__ float hs[2][BB][KC + 4];
    __shared__ float ws[2][NPB][KC + 4];
    float* as_ep = &ws[0][0][0];  // epilogue staging [64 cols][65], overlays ws (safe: phased)

    const int tid = threadIdx.x;
    const int warp = tid >> 5, lane = tid & 31;
    const int g8 = lane >> 2, tg = lane & 3;
    const int j0 = blockIdx.x * JPB;
    const int wm = (warp & 3) * 16;
    const int wn = (warp >> 2) * 32;

    float cstate[4] = {0.f, 0.f, 0.f, 0.f};  // thread-private cell state, exact fp32

    for (int t = 0; t < T_STEPS; t++) {
        const float* hprev = d_h[t & 1];

        float acc[4][4];
#pragma unroll
        for (int a = 0; a < 4; a++)
#pragma unroll
            for (int b = 0; b < 4; b++) acc[a][b] = 0.f;

        auto load_chunk = [&](int c, int buf) {
            int k0 = c * KC;
#pragma unroll
            for (int i = 0; i < 2; i++) {
                int q = tid + i * 256;
                int row = q >> 3, kq = q & 7;
                cpasync16(saddr(&hs[buf][row][kq * 4]),
                          hprev + (size_t)row * HH + k0 + kq * 4);
                int n = (row >> 4) * HH + j0 + (row & 15);
                cpasync16(saddr(&ws[buf][row][kq * 4]),
                          d_Whr + (size_t)n * HH + k0 + kq * 4);
            }
        };

        load_chunk(0, 0);
        CP_COMMIT();

        for (int c = 0; c < NCHUNK; c++) {
            if (c + 1 < NCHUNK) {
                load_chunk(c + 1, (c + 1) & 1);
                CP_COMMIT();
                CP_WAIT(1);
            } else {
                CP_WAIT(0);
            }
            __syncthreads();
            const int buf = c & 1;
#pragma unroll
            for (int kk = 0; kk < KC; kk += 8) {
                unsigned a0 = __float_as_uint(hs[buf][wm + g8][kk + tg]);
                unsigned a1 = __float_as_uint(hs[buf][wm + 8 + g8][kk + tg]);
                unsigned a2 = __float_as_uint(hs[buf][wm + g8][kk + tg + 4]);
                unsigned a3 = __float_as_uint(hs[buf][wm + 8 + g8][kk + tg + 4]);
#pragma unroll
                for (int ni = 0; ni < 4; ni++) {
                    unsigned b0 = __float_as_uint(ws[buf][wn + ni * 8 + g8][kk + tg]);
                    unsigned b1 = __float_as_uint(ws[buf][wn + ni * 8 + g8][kk + tg + 4]);
                    mma_tf32(acc[ni][0], acc[ni][1], acc[ni][2], acc[ni][3],
                             a0, a1, a2, a3, b0, b1);
                }
            }
            __syncthreads();
        }

        // stage A[col][row] into smem (overlay on ws; all mma reads of ws are done)
#pragma unroll
        for (int ni = 0; ni < 4; ni++) {
            int colb = wn + ni * 8 + 2 * tg;
            as_ep[(size_t)colb * 65 + wm + g8]           = acc[ni][0];
            as_ep[(size_t)(colb + 1) * 65 + wm + g8]     = acc[ni][1];
            as_ep[(size_t)colb * 65 + wm + 8 + g8]       = acc[ni][2];
            as_ep[(size_t)(colb + 1) * 65 + wm + 8 + g8] = acc[ni][3];
        }
        __syncthreads();

        // gate math + state update. pair p: jj = p&15 (lane-contiguous for coalesced Gx), b = p>>4
        const float* gx = d_Gx + (size_t)t * BB * NG;
        float* hnext = d_h[(t + 1) & 1];
#pragma unroll
        for (int i = 0; i < 4; i++) {
            int p = tid + i * 256;
            int jj = p & 15;
            int b = p >> 4;
            size_t gb = (size_t)b * NG + j0 + jj;
            float af = as_ep[(size_t)(0 * 16 + jj) * 65 + b] + gx[gb + 0 * HH];
            float ai = as_ep[(size_t)(1 * 16 + jj) * 65 + b] + gx[gb + 1 * HH];
            float ac = as_ep[(size_t)(2 * 16 + jj) * 65 + b] + gx[gb + 2 * HH];
            float ao = as_ep[(size_t)(3 * 16 + jj) * 65 + b] + gx[gb + 3 * HH];
            float fg = 1.f / (1.f + __expf(-af));
            float ig = 1.f / (1.f + __expf(-ai));
            float cg = tanhf(ac);
            float og = 1.f / (1.f + __expf(-ao));
            float cn = fg * cstate[i] + ig * cg;
            cstate[i] = cn;
            float hn = og * tanhf(cn);
            hnext[(size_t)b * HH + j0 + jj] = __uint_as_float(f2tf32(hn));
            if (t == T_STEPS - 1) d_hfin[(size_t)b * HH + j0 + jj] = hn;
        }

        if (t < T_STEPS - 1) {
            __threadfence();
            __syncthreads();
            if (tid == 0) {
                atomicAdd(&d_bar[t], 1);
                while (atomicAdd(&d_bar[t], 0) < GBLK) {}
                __threadfence();
            }
            __syncthreads();
        }
    }
}

// ---------------- final FC: out[b][n] = hfin[b] . Wfc[n] + bfc[n] (exact fp32) ----------------
__global__ void k_fc(const float* __restrict__ Wfc, const float* __restrict__ bfc,
                     float* __restrict__ out) {
    int b = blockIdx.x, n = blockIdx.y;
    const float* h = d_hfin + (size_t)b * HH;
    const float* w = Wfc + (size_t)n * HH;
    float s = 0.f;
    for (int k = threadIdx.x; k < HH; k += 128) s += h[k] * w[k];
#pragma unroll
    for (int o = 16; o > 0; o >>= 1) s += __shfl_down_sync(0xFFFFFFFFu, s, o);
    __shared__ float red[4];
    if ((threadIdx.x & 31) == 0) red[threadIdx.x >> 5] = s;
    __syncthreads();
    if (threadIdx.x == 0)
        out[b * NCLS + n] = red[0] + red[1] + red[2] + red[3] + bfc[n];
}

// ---------------- launch ----------------
extern "C" void kernel_launch(void* const* d_in, const int* in_sizes, int n_in,
                              void* d_out, int out_size) {
    const float* X   = (const float*)d_in[0];
    const float* Wf  = (const float*)d_in[1];
    const float* bf  = (const float*)d_in[2];
    const float* Wi  = (const float*)d_in[3];
    const float* bi  = (const float*)d_in[4];
    const float* Wc  = (const float*)d_in[5];
    const float* bc  = (const float*)d_in[6];
    const float* Wo  = (const float*)d_in[7];
    const float* bo  = (const float*)d_in[8];
    const float* Wfc = (const float*)d_in[9];
    const float* bfc = (const float*)d_in[10];

    k_init<<<64, 256>>>();
    {
        size_t tot = (size_t)4 * HH * DD;
        k_prep_w<<<(unsigned)((tot + 255) / 256), 256>>>(Wf, Wi, Wc, Wo);
    }
    {
        size_t tot = (size_t)BB * T_STEPS * EE;
        k_prep_x<<<(unsigned)((tot + 255) / 256), 256>>>(X);
    }
    k_gx_gemm<<<dim3(NG / XBN, (BB * T_STEPS) / XBM), 256>>>(bf, bi, bc, bo);
    k_lstm_rec<<<GBLK, 256>>>();
    k_fc<<<dim3(BB, NCLS), 128>>>(Wfc, bfc, (float*)d_out);
}

// round 2
// speedup vs baseline: 1.4125x; 1.4125x over previous
#include <cuda_runtime.h>
#include <cstdint>
#include <cstddef>

// ---------------- problem constants ----------------
#define T_STEPS 512
#define BB      64
#define EE      512
#define HH      1024
#define DD      1536
#define NG      4096      // 4*H gate columns (order: f, i, c, o)
#define NCLS    10

// ---------------- recurrent kernel config ----------------
#define GBLK 128          // persistent grid size (<= #SMs, co-resident)
#define JPB  8            // j (hidden units) per block -> 32 gate-cols
#define HSTR 264          // smem h row stride in floats (bank-conflict-free)
#define HBUF (64 * HSTR)  // floats per h buffer (16896)

// ---------------- x-GEMM config ----------------
#define XBM 128
#define XBN 128
#define XBK 16
#define XKCH (EE / XBK)   // 32

// ---------------- device scratch (allocation-free) ----------------
__device__ float d_Gx[(size_t)T_STEPS * BB * NG];   // x-side gate preacts [t][b][n]
__device__ float d_Xr[(size_t)BB * T_STEPS * EE];   // tf32-rounded input
__device__ float d_Wr2[(size_t)NG * HH];            // recurrent weights, per-thread frag layout
__device__ float d_Wxr[(size_t)NG * EE];            // tf32-rounded input weights [n][e]
__device__ float d_h[2][BB * HH];                   // double-buffered hidden state (tf32, k-permuted)
__device__ float d_hfin[BB * HH];                   // exact fp32 final h (logical order)
__device__ int   d_barq[T_STEPS * 4];               // per-step per-quarter barrier counters

// ---------------- helpers ----------------
__device__ __forceinline__ unsigned f2tf32(float x) {
    unsigned r;
    asm("cvt.rna.tf32.f32 %0, %1;" : "=r"(r) : "f"(x));
    return r;
}

__device__ __forceinline__ void mma_tf32(float& c0, float& c1, float& c2, float& c3,
                                         unsigned a0, unsigned a1, unsigned a2, unsigned a3,
                                         unsigned b0, unsigned b1) {
    asm volatile(
        "mma.sync.aligned.m16n8k8.row.col.f32.tf32.tf32.f32 "
        "{%0,%1,%2,%3},{%4,%5,%6,%7},{%8,%9},{%0,%1,%2,%3};"
        : "+f"(c0), "+f"(c1), "+f"(c2), "+f"(c3)
        : "r"(a0), "r"(a1), "r"(a2), "r"(a3), "r"(b0), "r"(b1));
}

__device__ __forceinline__ uint32_t saddr(const void* p) {
    return (uint32_t)__cvta_generic_to_shared(p);
}
__device__ __forceinline__ void cpasync16(uint32_t dst, const void* src) {
    asm volatile("cp.async.cg.shared.global [%0], [%1], 16;" :: "r"(dst), "l"(src));
}
#define CP_COMMIT() asm volatile("cp.async.commit_group;")
#define CP_WAIT(N)  asm volatile("cp.async.wait_group %0;" :: "n"(N))

__device__ __forceinline__ void mbar_wait(uint32_t mbar, unsigned phase) {
    asm volatile(
        "{\n\t"
        ".reg .pred P;\n\t"
        "LW%=:\n\t"
        "mbarrier.try_wait.parity.acquire.cta.shared::cta.b64 P, [%0], %1, 0x989680;\n\t"
        "@P bra LD%=;\n\t"
        "bra LW%=;\n\t"
        "LD%=:\n\t"
        "}"
        :: "r"(mbar), "r"(phase) : "memory");
}

// issue one 64KB h chunk: 64 rows x 1KB bulk copies into smem buffer
__device__ __forceinline__ void issue_chunk(uint32_t mbar, uint32_t dst_row0,
                                            const float* hsrc, int c_abs) {
    asm volatile("mbarrier.arrive.expect_tx.shared::cta.b64 _, [%0], %1;"
                 :: "r"(mbar), "r"(65536) : "memory");
    const char* src = (const char*)hsrc + (size_t)c_abs * 1024;
    uint32_t dst = dst_row0;
#pragma unroll 4
    for (int b = 0; b < 64; b++) {
        asm volatile(
            "cp.async.bulk.shared::cta.global.mbarrier::complete_tx::bytes [%0], [%1], %2, [%3];"
            :: "r"(dst), "l"(src), "r"(1024), "r"(mbar) : "memory");
        src += 4096;       // row stride in gmem (1024 floats)
        dst += 1056;       // row stride in smem (264 floats)
    }
}

// ---------------- init: zero barrier counters + h buffers ----------------
__global__ void k_init() {
    int i = blockIdx.x * blockDim.x + threadIdx.x;
    if (i < T_STEPS * 4) d_barq[i] = 0;
    for (int j = i; j < BB * HH; j += gridDim.x * blockDim.x) {
        d_h[0][j] = 0.f;
        d_h[1][j] = 0.f;
    }
}

// ---------------- prep: split + tf32-round weights ----------------
// x-part -> d_Wxr [n][e]. h-part -> d_Wr2 in per-thread mma-B-fragment layout:
//   block bid owns j in [bid*8, bid*8+8); warp w = ng*4+kq (ng = g>>1, kq = k-quarter
//   within a 256-chunk); lane = jj*4 + (k&3); reg r = ntl*64 + cc*16 + s*2 + pair
//   where cc = chunk rotated by block quarter, s = (k>>3)&7, pair = (k>>2)&1.
__global__ void k_prep_w(const float* __restrict__ Wf, const float* __restrict__ Wi,
                         const float* __restrict__ Wc, const float* __restrict__ Wo) {
    size_t idx = (size_t)blockIdx.x * blockDim.x + threadIdx.x;
    if (idx >= (size_t)4 * HH * DD) return;
    int d   = (int)(idx % DD);
    int rem = (int)(idx / DD);
    int j   = rem % HH;
    int g   = rem / HH;
    const float* W = (g == 0) ? Wf : (g == 1) ? Wi : (g == 2) ? Wc : Wo;
    float vr = __uint_as_float(f2tf32(W[(size_t)j * DD + d]));
    if (d < EE) {
        int n = g * HH + j;
        d_Wxr[(size_t)n * EE + d] = vr;
    } else {
        int k = d - EE;
        int bid = j >> 3, jj = j & 7;
        int cstart = bid >> 5;
        int cc = ((k >> 8) - cstart) & 3;
        int kq = (k >> 6) & 3;
        int s  = (k >> 3) & 7;
        int pair = (k >> 2) & 1;
        int tg = k & 3;
        int ng = g >> 1, ntl = g & 1;
        int w = ng * 4 + kq;
        int lane = (jj << 2) | tg;
        int r = ntl * 64 + cc * 16 + s * 2 + pair;
        d_Wr2[(((size_t)bid * 8 + w) * 32 + lane) * 128 + r] = vr;
    }
}

__global__ void k_prep_x(const float* __restrict__ X) {
    size_t idx = (size_t)blockIdx.x * blockDim.x + threadIdx.x;
    if (idx < (size_t)BB * T_STEPS * EE)
        d_Xr[idx] = __uint_as_float(f2tf32(X[idx]));
}

// ---------------- x-side GEMM: Gx[t][b][n] = X @ Wx^T + bias ----------------
__global__ void __launch_bounds__(256) k_gx_gemm(const float* __restrict__ bf, const float* __restrict__ bi,
                                                 const float* __restrict__ bc, const float* __restrict__ bo) {
    __shared__ float As[2][XBM][XBK + 4];
    __shared__ float Bs[2][XBN][XBK + 4];

    const int tid = threadIdx.x;
    const int warp = tid >> 5, lane = tid & 31;
    const int g8 = lane >> 2, tg = lane & 3;
    const int m0 = blockIdx.y * XBM;
    const int n0 = blockIdx.x * XBN;
    const int wm = (warp & 3) * 32;
    const int wn = (warp >> 2) * 64;

    float acc[2][8][4];
#pragma unroll
    for (int a = 0; a < 2; a++)
#pragma unroll
        for (int b = 0; b < 8; b++)
#pragma unroll
            for (int c = 0; c < 4; c++) acc[a][b][c] = 0.f;

    auto load_chunk = [&](int c, int buf) {
        int k0 = c * XBK;
#pragma unroll
        for (int i = 0; i < 2; i++) {
            int q = tid + i * 256;
            int row = q >> 2, kq = q & 3;
            cpasync16(saddr(&As[buf][row][kq * 4]),
                      d_Xr + (size_t)(m0 + row) * EE + k0 + kq * 4);
            cpasync16(saddr(&Bs[buf][row][kq * 4]),
                      d_Wxr + (size_t)(n0 + row) * EE + k0 + kq * 4);
        }
    };

    load_chunk(0, 0);
    CP_COMMIT();

    for (int c = 0; c < XKCH; c++) {
        if (c + 1 < XKCH) {
            load_chunk(c + 1, (c + 1) & 1);
            CP_COMMIT();
            CP_WAIT(1);
        } else {
            CP_WAIT(0);
        }
        __syncthreads();
        const int buf = c & 1;
#pragma unroll
        for (int kk = 0; kk < XBK; kk += 8) {
            unsigned a[2][4];
#pragma unroll
            for (int mi = 0; mi < 2; mi++) {
                a[mi][0] = __float_as_uint(As[buf][wm + mi * 16 + g8][kk + tg]);
                a[mi][1] = __float_as_uint(As[buf][wm + mi * 16 + 8 + g8][kk + tg]);
                a[mi][2] = __float_as_uint(As[buf][wm + mi * 16 + g8][kk + tg + 4]);
                a[mi][3] = __float_as_uint(As[buf][wm + mi * 16 + 8 + g8][kk + tg + 4]);
            }
#pragma unroll
            for (int ni = 0; ni < 8; ni++) {
                unsigned b0 = __float_as_uint(Bs[buf][wn + ni * 8 + g8][kk + tg]);
                unsigned b1 = __float_as_uint(Bs[buf][wn + ni * 8 + g8][kk + tg + 4]);
                mma_tf32(acc[0][ni][0], acc[0][ni][1], acc[0][ni][2], acc[0][ni][3],
                         a[0][0], a[0][1], a[0][2], a[0][3], b0, b1);
                mma_tf32(acc[1][ni][0], acc[1][ni][1], acc[1][ni][2], acc[1][ni][3],
                         a[1][0], a[1][1], a[1][2], a[1][3], b0, b1);
            }
        }
        __syncthreads();
    }

#pragma unroll
    for (int mi = 0; mi < 2; mi++) {
        int r0 = m0 + wm + mi * 16 + g8;
        int r1 = r0 + 8;
        size_t o0 = ((size_t)(r0 & (T_STEPS - 1)) * BB + (r0 >> 9)) * NG;
        size_t o1 = ((size_t)(r1 & (T_STEPS - 1)) * BB + (r1 >> 9)) * NG;
#pragma unroll
        for (int ni = 0; ni < 8; ni++) {
            int col = n0 + wn + ni * 8 + 2 * tg;
            int g = col >> 10;
            int jj = col & (HH - 1);
            const float* bp = (g == 0) ? bf : (g == 1) ? bi : (g == 2) ? bc : bo;
            float bv0 = bp[jj], bv1 = bp[jj + 1];
            float2 v0 = make_float2(acc[mi][ni][0] + bv0, acc[mi][ni][1] + bv1);
            float2 v1 = make_float2(acc[mi][ni][2] + bv0, acc[mi][ni][3] + bv1);
            *(float2*)(d_Gx + o0 + col) = v0;
            *(float2*)(d_Gx + o1 + col) = v1;
        }
    }
}

// ---------------- persistent recurrent kernel ----------------
// 128 blocks, each owns 8 hidden units j (32 gate-cols). Weights live in registers
// (128 per thread, loaded once). h streamed via cp.async.bulk, 4 chunks of K=256,
// double-buffered, with per-block chunk rotation + quarter-grained grid barrier.
__global__ void __launch_bounds__(256, 1) k_lstm_rec() {
    extern __shared__ float smem[];
    float*    hs   = smem;                       // [2][64][HSTR]
    float*    Csm  = smem + 2 * HBUF;            // [4 kq][4 g][64 b][8 jj]
    uint64_t* mbar = (uint64_t*)(smem + 2 * HBUF + 4096 * 2);

    const int tid  = threadIdx.x;
    const int bid  = blockIdx.x;
    const int w    = tid >> 5, lane = tid & 31;
    const int g8   = lane >> 2, tg = lane & 3;
    const int ng   = w >> 2, kq = w & 3;
    const int j0   = bid * JPB;
    const int cstart = bid >> 5;

    const uint32_t mb0 = saddr(&mbar[0]);
    const uint32_t mb1 = saddr(&mbar[1]);
    const uint32_t hsb = saddr(hs);

    if (tid == 0) {
        asm volatile("mbarrier.init.shared::cta.b64 [%0], 1;" :: "r"(mb0));
        asm volatile("mbarrier.init.shared::cta.b64 [%0], 1;" :: "r"(mb1));
        asm volatile("fence.proxy.async.shared::cta;" ::: "memory");
    }
    __syncthreads();

    // load this thread's weight fragments into registers (one-time)
    float breg[128];
    {
        const float4* wp = (const float4*)(d_Wr2 + (((size_t)bid * 8 + w) * 32 + lane) * 128);
#pragma unroll
        for (int i = 0; i < 32; i++) *(float4*)&breg[i * 4] = wp[i];
    }

    float cst[2] = {0.f, 0.f};
    unsigned ph[2] = {0u, 0u};

    for (int t = 0; t < T_STEPS; t++) {
        const float* hprev = d_h[t & 1];

        if (tid == 0) {
#pragma unroll
            for (int cc = 0; cc < 2; cc++) {
                int ca = (cc + cstart) & 3;
                if (t > 0) {
                    volatile int* p = d_barq + (t - 1) * 4 + ca;
                    while (*p < 32) {}
                }
                issue_chunk(cc ? mb1 : mb0, hsb + cc * (HBUF * 4), hprev, ca);
            }
        }

        // prefetch x-side preactivations for this step (hidden under GEMM)
        const float* gx = d_Gx + (size_t)t * BB * NG;
        float gxv[2][4];
#pragma unroll
        for (int i = 0; i < 2; i++) {
            int o = tid + i * 256;
            int b = o >> 3, jj = o & 7;
#pragma unroll
            for (int g = 0; g < 4; g++)
                gxv[i][g] = __ldg(gx + (size_t)b * NG + g * HH + j0 + jj);
        }

        float acc[2][4][4];
#pragma unroll
        for (int a = 0; a < 2; a++)
#pragma unroll
            for (int b = 0; b < 4; b++)
#pragma unroll
                for (int c = 0; c < 4; c++) acc[a][b][c] = 0.f;

#pragma unroll
        for (int cc = 0; cc < 4; cc++) {
            const int bf = cc & 1;
            mbar_wait(bf ? mb1 : mb0, ph[bf]);
            ph[bf] ^= 1;
            const float* hb = hs + bf * HBUF + kq * 64;
#pragma unroll
            for (int s = 0; s < 8; s++) {
#pragma unroll
                for (int mt = 0; mt < 4; mt++) {
                    float2 xa = *(const float2*)(hb + (mt * 16 + g8) * HSTR + s * 8 + 2 * tg);
                    float2 xb = *(const float2*)(hb + (mt * 16 + 8 + g8) * HSTR + s * 8 + 2 * tg);
#pragma unroll
                    for (int ntl = 0; ntl < 2; ntl++) {
                        const int r = ntl * 64 + cc * 16 + s * 2;
                        mma_tf32(acc[ntl][mt][0], acc[ntl][mt][1], acc[ntl][mt][2], acc[ntl][mt][3],
                                 __float_as_uint(xa.x), __float_as_uint(xb.x),
                                 __float_as_uint(xa.y), __float_as_uint(xb.y),
                                 __float_as_uint(breg[r]), __float_as_uint(breg[r + 1]));
                    }
                }
            }
            __syncthreads();
            if (cc < 2 && tid == 0) {
                int ca = (cc + 2 + cstart) & 3;
                if (t > 0) {
                    volatile int* p = d_barq + (t - 1) * 4 + ca;
                    while (*p < 32) {}
                }
                issue_chunk(bf ? mb1 : mb0, hsb + bf * (HBUF * 4), hprev, ca);
            }
        }

        // stage accumulators: Csm[kq][g][b][jj]
#pragma unroll
        for (int ntl = 0; ntl < 2; ntl++) {
            const int g = ng * 2 + ntl;
#pragma unroll
            for (int mt = 0; mt < 4; mt++) {
                float* cp = Csm + ((size_t)(kq * 4 + g) * 64 + mt * 16 + g8) * 8 + 2 * tg;
                *(float2*)cp        = make_float2(acc[ntl][mt][0], acc[ntl][mt][1]);
                *(float2*)(cp + 64) = make_float2(acc[ntl][mt][2], acc[ntl][mt][3]);
            }
        }
        __syncthreads();

        // epilogue: reduce 4 k-quarters, add Gx, gate math, update c, write h
        float* hnext = d_h[(t + 1) & 1];
#pragma unroll
        for (int i = 0; i < 2; i++) {
            int o = tid + i * 256;
            int b = o >> 3, jj = o & 7;
            float a4[4];
#pragma unroll
            for (int g = 0; g < 4; g++) {
                float s = gxv[i][g];
#pragma unroll
                for (int q = 0; q < 4; q++)
                    s += Csm[((size_t)(q * 4 + g) * 64 + b) * 8 + jj];
                a4[g] = s;
            }
            float fg = 1.f / (1.f + __expf(-a4[0]));
            float ig = 1.f / (1.f + __expf(-a4[1]));
            float cg = tanhf(a4[2]);
            float og = 1.f / (1.f + __expf(-a4[3]));
            float cn = fg * cst[i] + ig * cg;
            cst[i] = cn;
            float hn = og * tanhf(cn);
            int pjj = 2 * (jj & 3) + (jj >> 2);  // k-permuted position within 8-group
            __stcg(hnext + (size_t)b * HH + j0 + pjj, __uint_as_float(f2tf32(hn)));
            if (t == T_STEPS - 1) d_hfin[(size_t)b * HH + j0 + jj] = hn;
        }

        __threadfence();
        __syncthreads();
        if (tid == 0 && t < T_STEPS - 1)
            atomicAdd(d_barq + t * 4 + cstart, 1);
    }
}

// ---------------- final FC: out[b][n] = hfin[b] . Wfc[n] + bfc[n] (exact fp32) ----------------
__global__ void k_fc(const float* __restrict__ Wfc, const float* __restrict__ bfc,
                     float* __restrict__ out) {
    int b = blockIdx.x, n = blockIdx.y;
    const float* h = d_hfin + (size_t)b * HH;
    const float* w = Wfc + (size_t)n * HH;
    float s = 0.f;
    for (int k = threadIdx.x; k < HH; k += 128) s += h[k] * w[k];
#pragma unroll
    for (int o = 16; o > 0; o >>= 1) s += __shfl_down_sync(0xFFFFFFFFu, s, o);
    __shared__ float red[4];
    if ((threadIdx.x & 31) == 0) red[threadIdx.x >> 5] = s;
    __syncthreads();
    if (threadIdx.x == 0)
        out[b * NCLS + n] = red[0] + red[1] + red[2] + red[3] + bfc[n];
}

// ---------------- launch ----------------
extern "C" void kernel_launch(void* const* d_in, const int* in_sizes, int n_in,
                              void* d_out, int out_size) {
    const float* X   = (const float*)d_in[0];
    const float* Wf  = (const float*)d_in[1];
    const float* bf  = (const float*)d_in[2];
    const float* Wi  = (const float*)d_in[3];
    const float* bi  = (const float*)d_in[4];
    const float* Wc  = (const float*)d_in[5];
    const float* bc  = (const float*)d_in[6];
    const float* Wo  = (const float*)d_in[7];
    const float* bo  = (const float*)d_in[8];
    const float* Wfc = (const float*)d_in[9];
    const float* bfc = (const float*)d_in[10];

    static int smem_set = 0;
    const int rec_smem = (2 * HBUF + 8192) * 4 + 16;
    if (!smem_set) {
        cudaFuncSetAttribute(k_lstm_rec, cudaFuncAttributeMaxDynamicSharedMemorySize, rec_smem);
        smem_set = 1;
    }

    k_init<<<64, 256>>>();
    {
        size_t tot = (size_t)4 * HH * DD;
        k_prep_w<<<(unsigned)((tot + 255) / 256), 256>>>(Wf, Wi, Wc, Wo);
    }
    {
        size_t tot = (size_t)BB * T_STEPS * EE;
        k_prep_x<<<(unsigned)((tot + 255) / 256), 256>>>(X);
    }
    k_gx_gemm<<<dim3(NG / XBN, (BB * T_STEPS) / XBM), 256>>>(bf, bi, bc, bo);
    k_lstm_rec<<<GBLK, 256, rec_smem>>>();
    k_fc<<<dim3(BB, NCLS), 128>>>(Wfc, bfc, (float*)d_out);
}

// round 5
// speedup vs baseline: 1.4587x; 1.0327x over previous
#include <cuda_runtime.h>
#include <cuda_fp16.h>
#include <cstdint>
#include <cstddef>

// ---------------- problem constants ----------------
#define T_STEPS 512
#define BB      64
#define EE      512
#define HH      1024
#define DD      1536
#define NG      4096      // 4*H gate columns (order: f, i, c, o)
#define NCLS    10

// ---------------- recurrent kernel config ----------------
#define GBLK 128          // persistent grid (<= #SMs, co-resident)
#define JPB  8            // hidden units per block -> 32 gate-cols
#define RSTR 264          // smem h row stride in halves (512B + 16B pad)
#define CHALVES (64 * RSTR)   // halves per chunk buffer (16896)
#define CBYTES  (CHALVES * 2) // 33792

// ---------------- x-GEMM config (fp16) ----------------
#define XBM 128
#define XBN 128
#define XBK 32
#define XSTR 40           // smem row stride in halves (64B + 16B pad)
#define XKCH (EE / XBK)   // 16

// ---------------- device scratch (allocation-free) ----------------
__device__ float    d_Gx[(size_t)T_STEPS * BB * NG];   // x-side gate preacts [t][b][n] fp32
__device__ __half   d_X16[(size_t)BB * T_STEPS * EE];  // fp16 input
__device__ unsigned d_Wh16[(size_t)NG * HH / 2];       // recurrent weights, per-thread frag (half2 packed)
__device__ __half   d_Wx16[(size_t)NG * EE];           // fp16 input weights [n][e]
__device__ __half   d_hh[2][4 * 64 * 256];             // double-buffered hidden state, chunk-major [c][b][k]
__device__ float    d_hfin[BB * HH];                   // exact fp32 final h
__device__ int      d_barq[T_STEPS * 4];               // per-step per-quarter flags

// ---------------- helpers ----------------
__device__ __forceinline__ void mma_fp16(float& c0, float& c1, float& c2, float& c3,
                                         unsigned a0, unsigned a1, unsigned a2, unsigned a3,
                                         unsigned b0, unsigned b1) {
    asm volatile(
        "mma.sync.aligned.m16n8k16.row.col.f32.f16.f16.f32 "
        "{%0,%1,%2,%3},{%4,%5,%6,%7},{%8,%9},{%0,%1,%2,%3};"
        : "+f"(c0), "+f"(c1), "+f"(c2), "+f"(c3)
        : "r"(a0), "r"(a1), "r"(a2), "r"(a3), "r"(b0), "r"(b1));
}

__device__ __forceinline__ uint32_t saddr(const void* p) {
    return (uint32_t)__cvta_generic_to_shared(p);
}
__device__ __forceinline__ void cpasync16(uint32_t dst, const void* src) {
    asm volatile("cp.async.cg.shared.global [%0], [%1], 16;" :: "r"(dst), "l"(src));
}
#define CP_COMMIT() asm volatile("cp.async.commit_group;")
#define CP_WAIT(N)  asm volatile("cp.async.wait_group %0;" :: "n"(N))

__device__ __forceinline__ void mbar_wait(uint32_t mbar, unsigned phase) {
    asm volatile(
        "{\n\t"
        ".reg .pred P;\n\t"
        "LW%=:\n\t"
        "mbarrier.try_wait.parity.acquire.cta.shared::cta.b64 P, [%0], %1, 0x989680;\n\t"
        "@P bra LD%=;\n\t"
        "bra LW%=;\n\t"
        "LD%=:\n\t"
        "}"
        :: "r"(mbar), "r"(phase) : "memory");
}

__device__ __forceinline__ float tanh_fast(float x) {
    float r;
    asm("tanh.approx.f32 %0, %1;" : "=f"(r) : "f"(x));
    return r;
}
__device__ __forceinline__ float sig_fast(float x) {
    return 0.5f + 0.5f * tanh_fast(0.5f * x);
}

// ---------------- init ----------------
__global__ void k_init() {
    int i = blockIdx.x * blockDim.x + threadIdx.x;
    if (i < T_STEPS * 4) d_barq[i] = 0;
    unsigned* h = (unsigned*)&d_hh[0][0];
    for (int j = i; j < 2 * 4 * 64 * 256 / 2; j += gridDim.x * blockDim.x) h[j] = 0u;
}

// ---------------- prep: split + convert weights to fp16 ----------------
// h-part packed into per-thread mma-B fragments (m16n8k16), with per-block chunk rotation.
__global__ void k_prep_w(const float* __restrict__ Wf, const float* __restrict__ Wi,
                         const float* __restrict__ Wc, const float* __restrict__ Wo) {
    size_t idx = (size_t)blockIdx.x * blockDim.x + threadIdx.x;
    size_t total = (size_t)4 * HH * (DD / 2);
    if (idx >= total) return;
    int d2  = (int)(idx % (DD / 2));
    int rem = (int)(idx / (DD / 2));
    int j   = rem % HH;
    int g   = rem / HH;
    int d   = 2 * d2;
    const float* W = (g == 0) ? Wf : (g == 1) ? Wi : (g == 2) ? Wc : Wo;
    float v0 = W[(size_t)j * DD + d];
    float v1 = W[(size_t)j * DD + d + 1];
    __half h0 = __float2half_rn(v0), h1 = __float2half_rn(v1);
    if (d < EE) {
        int n = g * HH + j;
        *(__half2*)(d_Wx16 + (size_t)n * EE + d) = __halves2half2(h0, h1);
    } else {
        int k = d - EE;                 // even
        int bid = j >> 3, jj = j & 7;
        int cstart = bid >> 5;
        int cc = ((k >> 8) - cstart) & 3;
        int k256 = k & 255;
        int sk = k256 >> 6;
        int s  = (k256 >> 4) & 3;
        int kk = k256 & 15;
        int breg = kk >> 3;
        int tg = (kk & 7) >> 1;
        int nh = g >> 1, ntl = g & 1;
        int w = nh * 4 + sk;
        int lane = (jj << 2) | tg;
        int u = cc * 16 + s * 4 + ntl * 2 + breg;
        unsigned pk = ((unsigned)__half_as_ushort(h1) << 16) |
                      (unsigned)__half_as_ushort(h0);   // lo = smaller k
        d_Wh16[(((size_t)bid * 8 + w) * 32 + lane) * 64 + u] = pk;
    }
}

__global__ void k_prep_x(const float* __restrict__ X) {
    size_t idx = (size_t)blockIdx.x * blockDim.x + threadIdx.x;
    if (idx < (size_t)BB * T_STEPS * EE / 2) {
        float2 v = ((const float2*)X)[idx];
        ((__half2*)d_X16)[idx] = __halves2half2(__float2half_rn(v.x), __float2half_rn(v.y));
    }
}

// ---------------- x-side GEMM (fp16): Gx[t][b][n] = X @ Wx^T + bias ----------------
__global__ void __launch_bounds__(256) k_gx_gemm(const float* __restrict__ bf, const float* __restrict__ bi,
                                                 const float* __restrict__ bc, const float* __restrict__ bo) {
    __shared__ __half As[2][XBM][XSTR];
    __shared__ __half Bs[2][XBN][XSTR];

    const int tid = threadIdx.x;
    const int warp = tid >> 5, lane = tid & 31;
    const int g8 = lane >> 2, tg = lane & 3;
    const int m0 = blockIdx.y * XBM;
    const int n0 = blockIdx.x * XBN;
    const int wm = (warp & 3) * 32;
    const int wn = (warp >> 2) * 64;

    float acc[2][8][4];
#pragma unroll
    for (int a = 0; a < 2; a++)
#pragma unroll
        for (int b = 0; b < 8; b++)
#pragma unroll
            for (int c = 0; c < 4; c++) acc[a][b][c] = 0.f;

    auto load_chunk = [&](int c, int buf) {
        int k0 = c * XBK;
#pragma unroll
        for (int i = 0; i < 2; i++) {
            int q = tid + i * 256;
            int row = q >> 2, kq = q & 3;
            cpasync16(saddr(&As[buf][row][kq * 8]),
                      d_X16 + (size_t)(m0 + row) * EE + k0 + kq * 8);
            cpasync16(saddr(&Bs[buf][row][kq * 8]),
                      d_Wx16 + (size_t)(n0 + row) * EE + k0 + kq * 8);
        }
    };

    load_chunk(0, 0);
    CP_COMMIT();

    for (int c = 0; c < XKCH; c++) {
        if (c + 1 < XKCH) {
            load_chunk(c + 1, (c + 1) & 1);
            CP_COMMIT();
            CP_WAIT(1);
        } else {
            CP_WAIT(0);
        }
        __syncthreads();
        const int buf = c & 1;
#pragma unroll
        for (int kk = 0; kk < XBK; kk += 16) {
            unsigned a[2][4];
#pragma unroll
            for (int mi = 0; mi < 2; mi++) {
                a[mi][0] = *(const unsigned*)&As[buf][wm + mi * 16 + g8][kk + 2 * tg];
                a[mi][1] = *(const unsigned*)&As[buf][wm + mi * 16 + 8 + g8][kk + 2 * tg];
                a[mi][2] = *(const unsigned*)&As[buf][wm + mi * 16 + g8][kk + 8 + 2 * tg];
                a[mi][3] = *(const unsigned*)&As[buf][wm + mi * 16 + 8 + g8][kk + 8 + 2 * tg];
            }
#pragma unroll
            for (int ni = 0; ni < 8; ni++) {
                unsigned b0 = *(const unsigned*)&Bs[buf][wn + ni * 8 + g8][kk + 2 * tg];
                unsigned b1 = *(const unsigned*)&Bs[buf][wn + ni * 8 + g8][kk + 8 + 2 * tg];
                mma_fp16(acc[0][ni][0], acc[0][ni][1], acc[0][ni][2], acc[0][ni][3],
                         a[0][0], a[0][1], a[0][2], a[0][3], b0, b1);
                mma_fp16(acc[1][ni][0], acc[1][ni][1], acc[1][ni][2], acc[1][ni][3],
                         a[1][0], a[1][1], a[1][2], a[1][3], b0, b1);
            }
        }
        __syncthreads();
    }

#pragma unroll
    for (int mi = 0; mi < 2; mi++) {
        int r0 = m0 + wm + mi * 16 + g8;
        int r1 = r0 + 8;
        size_t o0 = ((size_t)(r0 & (T_STEPS - 1)) * BB + (r0 >> 9)) * NG;
        size_t o1 = ((size_t)(r1 & (T_STEPS - 1)) * BB + (r1 >> 9)) * NG;
#pragma unroll
        for (int ni = 0; ni < 8; ni++) {
            int col = n0 + wn + ni * 8 + 2 * tg;
            int g = col >> 10;
            int jj = col & (HH - 1);
            const float* bp = (g == 0) ? bf : (g == 1) ? bi : (g == 2) ? bc : bo;
            float bv0 = bp[jj], bv1 = bp[jj + 1];
            float2 v0 = make_float2(acc[mi][ni][0] + bv0, acc[mi][ni][1] + bv1);
            float2 v1 = make_float2(acc[mi][ni][2] + bv0, acc[mi][ni][3] + bv1);
            *(float2*)(d_Gx + o0 + col) = v0;
            *(float2*)(d_Gx + o1 + col) = v1;
        }
    }
}

// ---------------- persistent recurrent kernel (warp-specialized) ----------------
// 128 blocks x 288 threads. Warps 0-7 compute (warp = n-half x k-slice), warp 8 produces.
// h fp16, chunk-major in gmem; 4-stage smem ring of 32KB chunks via full/empty mbarriers.
// Weights in registers (64 u32 fp16-pairs per thread).
__global__ void __launch_bounds__(288, 1) k_lstm_rec() {
    extern __shared__ char smemc[];
    __half*   hs   = (__half*)smemc;                             // [4][64][RSTR]
    float*    Csm  = (float*)(smemc + 4 * CBYTES);               // [4 sk][64 m][34]
    uint64_t* mbar = (uint64_t*)(smemc + 4 * CBYTES + 4 * 64 * 34 * 4);

    const int tid  = threadIdx.x;
    const int bid  = blockIdx.x;
    const int w    = tid >> 5, lane = tid & 31;
    const int g8   = lane >> 2, tg = lane & 3;
    const int j0   = bid * JPB;
    const int cstart = bid >> 5;

    uint32_t full_mb[4], empty_mb[4];
#pragma unroll
    for (int i = 0; i < 4; i++) {
        full_mb[i]  = saddr(&mbar[i]);
        empty_mb[i] = saddr(&mbar[4 + i]);
    }

    if (tid == 0) {
#pragma unroll
        for (int i = 0; i < 4; i++) {
            asm volatile("mbarrier.init.shared::cta.b64 [%0], 1;" :: "r"(full_mb[i]));
            asm volatile("mbarrier.init.shared::cta.b64 [%0], 8;" :: "r"(empty_mb[i]));
        }
        asm volatile("fence.proxy.async.shared::cta;" ::: "memory");
    }
    __syncthreads();

    if (w == 8) {
        // ---------------- producer warp ----------------
        for (int t = 0; t < T_STEPS; t++) {
            const __half* hsrc = &d_hh[t & 1][0];
#pragma unroll 1
            for (int cc = 0; cc < 4; cc++) {
                int ca = (cc + cstart) & 3;
                if (t > 0) {
                    mbar_wait(empty_mb[cc], (t - 1) & 1);
                    volatile int* p = d_barq + (t - 1) * 4 + ca;
                    while (*p < 32) {}
                    asm volatile("membar.gl;" ::: "memory");
                }
                if (lane == 0)
                    asm volatile("mbarrier.arrive.expect_tx.shared::cta.b64 _, [%0], %1;"
                                 :: "r"(full_mb[cc]), "r"(32768) : "memory");
                __syncwarp();
#pragma unroll
                for (int rr = 0; rr < 2; rr++) {
                    int r = lane + rr * 32;
                    uint32_t dst = saddr(hs) + cc * CBYTES + r * (RSTR * 2);
                    const __half* src = hsrc + ca * 16384 + r * 256;
                    asm volatile(
                        "cp.async.bulk.shared::cta.global.mbarrier::complete_tx::bytes [%0], [%1], %2, [%3];"
                        :: "r"(dst), "l"(src), "r"(512), "r"(full_mb[cc]) : "memory");
                }
            }
        }
        return;
    }

    // ---------------- compute warps (0-7) ----------------
    const int nh = w >> 2, sk = w & 3;

    unsigned wreg[64];
    {
        const uint4* wp = (const uint4*)(d_Wh16 + (((size_t)bid * 8 + w) * 32 + lane) * 64);
#pragma unroll
        for (int i = 0; i < 16; i++) *(uint4*)&wreg[i * 4] = wp[i];
    }

    // epilogue identity: thread handles (b, jj-pair)
    const int eb  = tid >> 2;
    const int ej2 = tid & 3;
    float2 cst = make_float2(0.f, 0.f);

    for (int t = 0; t < T_STEPS; t++) {
        // prefetch x-side preacts
        const float* gx = d_Gx + (size_t)t * BB * NG + (size_t)eb * NG + j0 + 2 * ej2;
        float2 gxv[4];
#pragma unroll
        for (int g = 0; g < 4; g++) gxv[g] = __ldg((const float2*)(gx + g * HH));

        float acc[2][4][4];
#pragma unroll
        for (int a = 0; a < 2; a++)
#pragma unroll
            for (int b = 0; b < 4; b++)
#pragma unroll
                for (int c = 0; c < 4; c++) acc[a][b][c] = 0.f;

#pragma unroll 1
        for (int cc = 0; cc < 4; cc++) {
            mbar_wait(full_mb[cc], t & 1);
            const __half* hb = hs + cc * CHALVES + sk * 64;
#pragma unroll
            for (int s = 0; s < 4; s++) {
                const int col = s * 16 + 2 * tg;
#pragma unroll
                for (int mt = 0; mt < 4; mt++) {
                    const __half* rp = hb + (mt * 16 + g8) * RSTR + col;
                    unsigned a0 = *(const unsigned*)rp;
                    unsigned a1 = *(const unsigned*)(rp + 8 * RSTR);
                    unsigned a2 = *(const unsigned*)(rp + 8);
                    unsigned a3 = *(const unsigned*)(rp + 8 * RSTR + 8);
#pragma unroll
                    for (int ntl = 0; ntl < 2; ntl++) {
                        const int u = cc * 16 + s * 4 + ntl * 2;
                        mma_fp16(acc[ntl][mt][0], acc[ntl][mt][1], acc[ntl][mt][2], acc[ntl][mt][3],
                                 a0, a1, a2, a3, wreg[u], wreg[u + 1]);
                    }
                }
            }
            __syncwarp();
            if (lane == 0)
                asm volatile("mbarrier.arrive.shared::cta.b64 _, [%0];"
                             :: "r"(empty_mb[cc]) : "memory");
        }

        // stage partials: Csm[sk][m][n(32) padded to 34]
#pragma unroll
        for (int ntl = 0; ntl < 2; ntl++) {
            const int nb = nh * 16 + ntl * 8 + 2 * tg;
#pragma unroll
            for (int mt = 0; mt < 4; mt++) {
                float* cp = Csm + (size_t)(sk * 64 + mt * 16 + g8) * 34 + nb;
                *(float2*)cp              = make_float2(acc[ntl][mt][0], acc[ntl][mt][1]);
                *(float2*)(cp + 8 * 34)   = make_float2(acc[ntl][mt][2], acc[ntl][mt][3]);
            }
        }
        asm volatile("bar.sync 1, 256;" ::: "memory");

        // epilogue: reduce 4 k-slices, gates, state update, write fp16 h
        {
            float2 a4[4];
#pragma unroll
            for (int g = 0; g < 4; g++) {
                float2 s = gxv[g];
#pragma unroll
                for (int q = 0; q < 4; q++) {
                    float2 v = *(const float2*)(Csm + (size_t)(q * 64 + eb) * 34 + g * 8 + 2 * ej2);
                    s.x += v.x; s.y += v.y;
                }
                a4[g] = s;
            }
            float fgx = sig_fast(a4[0].x), fgy = sig_fast(a4[0].y);
            float igx = sig_fast(a4[1].x), igy = sig_fast(a4[1].y);
            float cgx = tanh_fast(a4[2].x), cgy = tanh_fast(a4[2].y);
            float ogx = sig_fast(a4[3].x), ogy = sig_fast(a4[3].y);
            cst.x = fgx * cst.x + igx * cgx;
            cst.y = fgy * cst.y + igy * cgy;
            float hnx = ogx * tanh_fast(cst.x);
            float hny = ogy * tanh_fast(cst.y);
            __half2* hd = (__half2*)(&d_hh[(t + 1) & 1][0] +
                                     cstart * 16384 + eb * 256 + (j0 & 255) + 2 * ej2);
            *hd = __halves2half2(__float2half_rn(hnx), __float2half_rn(hny));
            if (t == T_STEPS - 1)
                *(float2*)(d_hfin + (size_t)eb * HH + j0 + 2 * ej2) = make_float2(hnx, hny);
        }

        asm volatile("bar.sync 1, 256;" ::: "memory");
        if (tid == 0 && t < T_STEPS - 1) {
            asm volatile("membar.gl;" ::: "memory");
            atomicAdd(d_barq + t * 4 + cstart, 1);
        }
    }
}

// ---------------- final FC (exact fp32) ----------------
__global__ void k_fc(const float* __restrict__ Wfc, const float* __restrict__ bfc,
                     float* __restrict__ out) {
    int b = blockIdx.x, n = blockIdx.y;
    const float* h = d_hfin + (size_t)b * HH;
    const float* w = Wfc + (size_t)n * HH;
    float s = 0.f;
    for (int k = threadIdx.x; k < HH; k += 128) s += h[k] * w[k];
#pragma unroll
    for (int o = 16; o > 0; o >>= 1) s += __shfl_down_sync(0xFFFFFFFFu, s, o);
    __shared__ float red[4];
    if ((threadIdx.x & 31) == 0) red[threadIdx.x >> 5] = s;
    __syncthreads();
    if (threadIdx.x == 0)
        out[b * NCLS + n] = red[0] + red[1] + red[2] + red[3] + bfc[n];
}

// ---------------- launch ----------------
extern "C" void kernel_launch(void* const* d_in, const int* in_sizes, int n_in,
                              void* d_out, int out_size) {
    const float* X   = (const float*)d_in[0];
    const float* Wf  = (const float*)d_in[1];
    const float* bf  = (const float*)d_in[2];
    const float* Wi  = (const float*)d_in[3];
    const float* bi  = (const float*)d_in[4];
    const float* Wc  = (const float*)d_in[5];
    const float* bc  = (const float*)d_in[6];
    const float* Wo  = (const float*)d_in[7];
    const float* bo  = (const float*)d_in[8];
    const float* Wfc = (const float*)d_in[9];
    const float* bfc = (const float*)d_in[10];

    const int rec_smem = 4 * CBYTES + 4 * 64 * 34 * 4 + 64;  // 135168 + 34816 + 64
    cudaFuncSetAttribute(k_lstm_rec, cudaFuncAttributeMaxDynamicSharedMemorySize, rec_smem);

    k_init<<<64, 256>>>();
    {
        size_t tot = (size_t)4 * HH * (DD / 2);
        k_prep_w<<<(unsigned)((tot + 255) / 256), 256>>>(Wf, Wi, Wc, Wo);
    }
    {
        size_t tot = (size_t)BB * T_STEPS * EE / 2;
        k_prep_x<<<(unsigned)((tot + 255) / 256), 256>>>(X);
    }
    k_gx_gemm<<<dim3(NG / XBN, (BB * T_STEPS) / XBM), 256>>>(bf, bi, bc, bo);
    k_lstm_rec<<<GBLK, 288, rec_smem>>>();
    k_fc<<<dim3(BB, NCLS), 128>>>(Wfc, bfc, (float*)d_out);
}